// round 2
// baseline (speedup 1.0000x reference)
#include <cuda_runtime.h>
#include <math.h>

#define C_    192
#define NHEAD 6
#define HDIM  32
#define BB    32
#define HH    64
#define WWID  64
#define NTOK  (BB*HH*WWID)      // 131072
#define QKVW  (3*C_)            // 576
#define MLPD  (4*C_)            // 768

// ---------------- static scratch (no allocations allowed) ----------------
// Lifetimes:
//   Y    : written by LN1, read by qkv-gemm            (phase 1-2)
//   QKV  : written by qkv-gemm, read by attn           (phase 2-3)
//   AO   : written by attn, read by lin-gemm           (phase 3-4)
//   XMID : written by lin-gemm, read by LN2 + mlp2     (phase 4-7)
//   Z    : written by LN2, read by mlp1                (phase 5-6)
//   H    : written by mlp1, read by mlp2               (phase 6-7)
// Aliases: Z reuses Y (Y dead after phase 2). AO reuses front of H
// (H not written until phase 6, AO dead after phase 4).
__device__ float g_YZ  [NTOK*C_];      // Y, then Z
__device__ float g_QKV [NTOK*QKVW];
__device__ float g_XMID[NTOK*C_];
__device__ float g_H   [NTOK*MLPD];    // front NTOK*C_ doubles as AO earlier

// ---------------- LayerNorm (one warp per token) ----------------
template<bool WINDOWED>
__global__ __launch_bounds__(256) void ln_kernel(
        const float* __restrict__ x,
        const float* __restrict__ gamma,
        const float* __restrict__ beta,
        float* __restrict__ y) {
    int warp = (blockIdx.x * blockDim.x + threadIdx.x) >> 5;
    int lane = threadIdx.x & 31;
    if (warp >= NTOK) return;

    long src;
    if (WINDOWED) {
        int p   = warp & 63;
        int win = (warp >> 6) & 63;
        int b   = warp >> 12;
        int r = p >> 3, c = p & 7;
        int wi = win >> 3, wj = win & 7;
        int h = (wi*8 + r + 4) & 63;   // undo roll(-4): y[hs] = x[(hs+4)%64]
        int w = (wj*8 + c + 4) & 63;
        src = (long)((b*64 + h)*64 + w);
    } else {
        src = warp;
    }
    const float* xr = x + src * C_;
    float v[6];
    float s = 0.f;
#pragma unroll
    for (int i = 0; i < 6; i++) { v[i] = xr[lane + 32*i]; s += v[i]; }
#pragma unroll
    for (int o = 16; o; o >>= 1) s += __shfl_xor_sync(0xffffffffu, s, o);
    float mean = s * (1.f / C_);
    float q = 0.f;
#pragma unroll
    for (int i = 0; i < 6; i++) { float d = v[i] - mean; q += d*d; }
#pragma unroll
    for (int o = 16; o; o >>= 1) q += __shfl_xor_sync(0xffffffffu, q, o);
    float inv = rsqrtf(q * (1.f / C_) + 1e-5f);

    float* yr = y + (long)warp * C_;
#pragma unroll
    for (int i = 0; i < 6; i++) {
        int ch = lane + 32*i;
        yr[ch] = (v[i] - mean) * inv * gamma[ch] + beta[ch];
    }
}

// ---------------- SIMT fp32 GEMM: C[M,N] = A[M,K] @ W[N,K]^T (+epilogue) ----------------
// BM=BN=64, BK=16, 256 threads, 4x4 per thread.
// EPI: 0 = +bias                                        (qkv)
//      1 = +bias, un-window/un-roll scatter, +residual  (lin)
//      2 = +bias, exact GELU                            (mlp1)
//      3 = +bias, +residual (same layout)               (mlp2)
template<int EPI>
__global__ __launch_bounds__(256) void gemm64(
        const float* __restrict__ A, const float* __restrict__ W,
        const float* __restrict__ bias, const float* __restrict__ res,
        float* __restrict__ out, int M, int N, int K) {
    __shared__ float As[16][68];
    __shared__ float Bs[16][68];
    int tid = threadIdx.x;
    int tx = tid & 15, ty = tid >> 4;
    int n0 = blockIdx.x * 64;
    long m0 = (long)blockIdx.y * 64;

    int lrow = tid >> 2;           // 0..63
    int lkg  = (tid & 3) * 4;      // 0,4,8,12
    const float* Ag = A + (m0 + lrow) * (long)K + lkg;
    const float* Wg = W + (long)(n0 + lrow) * K + lkg;

    float acc[4][4] = {};
    for (int k0 = 0; k0 < K; k0 += 16) {
        float4 av = *(const float4*)(Ag + k0);
        float4 wv = *(const float4*)(Wg + k0);
        As[lkg+0][lrow] = av.x; As[lkg+1][lrow] = av.y;
        As[lkg+2][lrow] = av.z; As[lkg+3][lrow] = av.w;
        Bs[lkg+0][lrow] = wv.x; Bs[lkg+1][lrow] = wv.y;
        Bs[lkg+2][lrow] = wv.z; Bs[lkg+3][lrow] = wv.w;
        __syncthreads();
#pragma unroll
        for (int kk = 0; kk < 16; kk++) {
            float4 a = *(const float4*)&As[kk][ty*4];
            float4 b = *(const float4*)&Bs[kk][tx*4];
            float ar[4] = {a.x, a.y, a.z, a.w};
            float br[4] = {b.x, b.y, b.z, b.w};
#pragma unroll
            for (int i = 0; i < 4; i++)
#pragma unroll
                for (int j = 0; j < 4; j++)
                    acc[i][j] += ar[i] * br[j];
        }
        __syncthreads();
    }

#pragma unroll
    for (int i = 0; i < 4; i++) {
        long m = m0 + ty*4 + i;
        long orow;
        if (EPI == 1) {
            // window-ordered row m -> pixel index (undo partition + roll(+4))
            int p   = (int)(m & 63);
            int win = (int)((m >> 6) & 63);
            int b   = (int)(m >> 12);
            int r = p >> 3, c = p & 7;
            int wi = win >> 3, wj = win & 7;
            int h = (wi*8 + r + 4) & 63;
            int w = (wj*8 + c + 4) & 63;
            orow = (long)((b*64 + h)*64 + w);
        } else {
            orow = m;
        }
#pragma unroll
        for (int j = 0; j < 4; j++) {
            int n = n0 + tx*4 + j;
            float v = acc[i][j] + bias[n];
            if (EPI == 1) {
                out[orow * (long)N + n] = res[orow * (long)N + n] + v;
            } else if (EPI == 2) {
                out[m * (long)N + n] = 0.5f * v * (1.f + erff(v * 0.70710678118654752f));
            } else if (EPI == 3) {
                out[m * (long)N + n] = v + res[m * (long)N + n];
            } else {
                out[m * (long)N + n] = v;
            }
        }
    }
}

// ---------------- windowed attention: one block per (window, head), 64 threads ----------------
__global__ __launch_bounds__(64) void attn_kernel(
        const float* __restrict__ qkv,
        const float* __restrict__ rpp,
        float* __restrict__ ao) {
    int wg   = blockIdx.x;          // b*64 + win
    int head = blockIdx.y;          // 0..5
    int t    = threadIdx.x;         // query token 0..63
    int win  = wg & 63;
    int wi = win >> 3, wj = win & 7;

    __shared__ float ks[64][36];
    __shared__ float vs[64][36];
    __shared__ float S[64][65];
    __shared__ float biasS[228];

    long rowbase = (long)(wg*64 + t) * QKVW;
    float q[32];
    {
        const float4* qp = (const float4*)(qkv + rowbase + head*HDIM);
        const float4* kp = (const float4*)(qkv + rowbase + (NHEAD + head)*HDIM);
        const float4* vp = (const float4*)(qkv + rowbase + (2*NHEAD + head)*HDIM);
#pragma unroll
        for (int d4 = 0; d4 < 8; d4++) {
            float4 qv = qp[d4];
            q[4*d4+0] = qv.x; q[4*d4+1] = qv.y; q[4*d4+2] = qv.z; q[4*d4+3] = qv.w;
            ((float4*)&ks[t][0])[d4] = kp[d4];
            ((float4*)&vs[t][0])[d4] = vp[d4];
        }
    }
    for (int i = t; i < 225; i += 64) biasS[i] = rpp[head*225 + i];
    __syncthreads();

    const float scale = 0.17677669529663687f;  // 1/sqrt(32)
    int r1 = t >> 3, c1 = t & 7;
    bool mi = (wi == 7), mj = (wj == 7);
    bool q_r = (r1 < 4), q_c = (c1 < 4);

    float mx = -1e30f;
#pragma unroll 4
    for (int j = 0; j < 64; j++) {
        int r2 = j >> 3, c2 = j & 7;
        const float4* kr = (const float4*)&ks[j][0];
        float s = 0.f;
#pragma unroll
        for (int d4 = 0; d4 < 8; d4++) {
            float4 kv = kr[d4];
            s += q[4*d4+0]*kv.x + q[4*d4+1]*kv.y + q[4*d4+2]*kv.z + q[4*d4+3]*kv.w;
        }
        s = s * scale + biasS[(r1 - r2 + 7)*15 + (c1 - c2 + 7)];
        bool msk = (mi && (q_r != (r2 < 4))) || (mj && (q_c != (c2 < 4)));
        if (msk) s = -1e30f;
        S[t][j] = s;
        mx = fmaxf(mx, s);
    }
    float sum = 0.f;
#pragma unroll 4
    for (int j = 0; j < 64; j++) {
        float p = __expf(S[t][j] - mx);
        S[t][j] = p;
        sum += p;
    }
    float o[32] = {};
#pragma unroll 2
    for (int j = 0; j < 64; j++) {
        float p = S[t][j];
        const float4* vr = (const float4*)&vs[j][0];
#pragma unroll
        for (int d4 = 0; d4 < 8; d4++) {
            float4 vv = vr[d4];
            o[4*d4+0] += p*vv.x; o[4*d4+1] += p*vv.y;
            o[4*d4+2] += p*vv.z; o[4*d4+3] += p*vv.w;
        }
    }
    float inv = 1.f / sum;
    float* orow = ao + (long)(wg*64 + t) * C_ + head*HDIM;
#pragma unroll
    for (int d4 = 0; d4 < 8; d4++) {
        float4 ov = make_float4(o[4*d4]*inv, o[4*d4+1]*inv, o[4*d4+2]*inv, o[4*d4+3]*inv);
        ((float4*)orow)[d4] = ov;
    }
}

// ---------------- launcher ----------------
extern "C" void kernel_launch(void* const* d_in, const int* in_sizes, int n_in,
                              void* d_out, int out_size) {
    const float* x      = (const float*)d_in[0];
    const float* ln1_g  = (const float*)d_in[1];
    const float* ln1_b  = (const float*)d_in[2];
    const float* qkv_w  = (const float*)d_in[3];
    const float* qkv_b  = (const float*)d_in[4];
    const float* rpp    = (const float*)d_in[5];
    const float* lin_w  = (const float*)d_in[6];
    const float* lin_b  = (const float*)d_in[7];
    const float* ln2_g  = (const float*)d_in[8];
    const float* ln2_b  = (const float*)d_in[9];
    const float* mlp_w1 = (const float*)d_in[10];
    const float* mlp_b1 = (const float*)d_in[11];
    const float* mlp_w2 = (const float*)d_in[12];
    const float* mlp_b2 = (const float*)d_in[13];
    float* out = (float*)d_out;

    float *YZ, *QKV, *XMID, *Hm;
    cudaGetSymbolAddress((void**)&YZ,   g_YZ);
    cudaGetSymbolAddress((void**)&QKV,  g_QKV);
    cudaGetSymbolAddress((void**)&XMID, g_XMID);
    cudaGetSymbolAddress((void**)&Hm,   g_H);
    float* AO = Hm;   // front NTOK*C_ of g_H, free until phase 6

    const int LN_BLOCKS = NTOK / 8;          // 8 warps (tokens) per 256-thread block
    const int MB = NTOK / 64;                // 2048 GEMM row-tiles

    // 1) LN1 + shift-roll + window partition
    ln_kernel<true><<<LN_BLOCKS, 256>>>(x, ln1_g, ln1_b, YZ);
    // 2) qkv projection (+bias)
    gemm64<0><<<dim3(QKVW/64, MB), 256>>>(YZ, qkv_w, qkv_b, nullptr, QKV, NTOK, QKVW, C_);
    // 3) windowed attention (rel bias + shift mask + softmax)
    attn_kernel<<<dim3(2048, NHEAD), 64>>>(QKV, rpp, AO);
    // 4) output projection + un-window/un-roll + residual -> XMID
    gemm64<1><<<dim3(C_/64, MB), 256>>>(AO, lin_w, lin_b, x, XMID, NTOK, C_, C_);
    // 5) LN2 (Z overwrites Y in g_YZ)
    ln_kernel<false><<<LN_BLOCKS, 256>>>(XMID, ln2_g, ln2_b, YZ);
    // 6) MLP up-projection + exact GELU (overwrites AO region of g_H)
    gemm64<2><<<dim3(MLPD/64, MB), 256>>>(YZ, mlp_w1, mlp_b1, nullptr, Hm, NTOK, MLPD, C_);
    // 7) MLP down-projection + residual -> final output
    gemm64<3><<<dim3(C_/64, MB), 256>>>(Hm, mlp_w2, mlp_b2, XMID, out, NTOK, C_, MLPD);
}

// round 3
// speedup vs baseline: 2.2236x; 2.2236x over previous
#include <cuda_runtime.h>
#include <math.h>

#define C_    192
#define NHEAD 6
#define HDIM  32
#define NTOK  (32*64*64)        // 131072
#define QKVW  (3*C_)            // 576
#define MLPD  (4*C_)            // 768

// ---------------- static scratch ----------------
__device__ float g_YZ  [NTOK*C_];      // Y (LN1 out), later Z (LN2 out)
__device__ float g_QKV [NTOK*QKVW];
__device__ float g_XMID[NTOK*C_];
__device__ float g_H   [NTOK*MLPD];    // front NTOK*C_ doubles as AO before phase 6

// ---------------- helpers ----------------
__device__ __forceinline__ unsigned f2tf32(float x) {
    unsigned r; asm("cvt.rna.tf32.f32 %0, %1;" : "=r"(r) : "f"(x)); return r;
}
__device__ __forceinline__ void mma_tf32(float* c, const unsigned* a, const unsigned* b) {
    asm volatile("mma.sync.aligned.m16n8k8.row.col.f32.tf32.tf32.f32 "
        "{%0,%1,%2,%3}, {%4,%5,%6,%7}, {%8,%9}, {%0,%1,%2,%3};"
        : "+f"(c[0]), "+f"(c[1]), "+f"(c[2]), "+f"(c[3])
        : "r"(a[0]), "r"(a[1]), "r"(a[2]), "r"(a[3]), "r"(b[0]), "r"(b[1]));
}

// ---------------- LayerNorm (one warp per token) ----------------
template<bool WINDOWED>
__global__ __launch_bounds__(256) void ln_kernel(
        const float* __restrict__ x,
        const float* __restrict__ gamma,
        const float* __restrict__ beta,
        float* __restrict__ y) {
    int warp = (blockIdx.x * blockDim.x + threadIdx.x) >> 5;
    int lane = threadIdx.x & 31;
    if (warp >= NTOK) return;

    long src;
    if (WINDOWED) {
        int p   = warp & 63;
        int win = (warp >> 6) & 63;
        int b   = warp >> 12;
        int r = p >> 3, c = p & 7;
        int wi = win >> 3, wj = win & 7;
        int h = (wi*8 + r + 4) & 63;
        int w = (wj*8 + c + 4) & 63;
        src = (long)((b*64 + h)*64 + w);
    } else {
        src = warp;
    }
    const float* xr = x + src * C_;
    float v[6];
    float s = 0.f;
#pragma unroll
    for (int i = 0; i < 6; i++) { v[i] = xr[lane + 32*i]; s += v[i]; }
#pragma unroll
    for (int o = 16; o; o >>= 1) s += __shfl_xor_sync(0xffffffffu, s, o);
    float mean = s * (1.f / C_);
    float q = 0.f;
#pragma unroll
    for (int i = 0; i < 6; i++) { float d = v[i] - mean; q += d*d; }
#pragma unroll
    for (int o = 16; o; o >>= 1) q += __shfl_xor_sync(0xffffffffu, q, o);
    float inv = rsqrtf(q * (1.f / C_) + 1e-5f);

    float* yr = y + (long)warp * C_;
#pragma unroll
    for (int i = 0; i < 6; i++) {
        int ch = lane + 32*i;
        yr[ch] = (v[i] - mean) * inv * gamma[ch] + beta[ch];
    }
}

// ---------------- tf32 tensor-core GEMM: C[M,N] = A[M,K] @ W[N,K]^T (+epilogue) ----------------
// BM=128, BN=64, BK=32. 256 threads = 8 warps (4m x 2n), warp tile 32x32.
// EPI: 0=+bias  1=+bias,unwindow+residual  2=+bias,GELU  3=+bias,residual
#define BKg 32
template<int EPI>
__global__ __launch_bounds__(256) void gemm_tc(
        const float* __restrict__ A, const float* __restrict__ W,
        const float* __restrict__ bias, const float* __restrict__ res,
        float* __restrict__ out, int M, int N, int K) {
    __shared__ unsigned As[128*36];   // [m][k], stride 36
    __shared__ unsigned Bs[64*36];    // [n][k], stride 36

    int tid  = threadIdx.x;
    int lane = tid & 31;
    int wid  = tid >> 5;
    int wm   = wid >> 1;     // 0..3
    int wn   = wid & 1;      // 0..1
    int g    = lane >> 2;    // 0..7
    int t    = lane & 3;     // 0..3

    int n0   = blockIdx.x * 64;
    long m0  = (long)blockIdx.y * 128;
    int nit  = K / BKg;

    // tile-load index precompute (A: 4 float4/thread, B: 2 float4/thread)
    int am[4], ak[4], bn[2], bk[2];
#pragma unroll
    for (int i = 0; i < 4; i++) { int idx = tid + 256*i; am[i] = idx >> 3; ak[i] = (idx & 7) * 4; }
#pragma unroll
    for (int i = 0; i < 2; i++) { int idx = tid + 256*i; bn[i] = idx >> 3; bk[i] = (idx & 7) * 4; }

    float4 pa[4], pb[2];
    auto load_tile = [&](int k0) {
#pragma unroll
        for (int i = 0; i < 4; i++)
            pa[i] = *(const float4*)(A + (m0 + am[i]) * (long)K + k0 + ak[i]);
#pragma unroll
        for (int i = 0; i < 2; i++)
            pb[i] = *(const float4*)(W + (long)(n0 + bn[i]) * K + k0 + bk[i]);
    };
    auto store_tile = [&]() {
#pragma unroll
        for (int i = 0; i < 4; i++) {
            unsigned* d = &As[am[i]*36 + ak[i]];
            d[0]=f2tf32(pa[i].x); d[1]=f2tf32(pa[i].y); d[2]=f2tf32(pa[i].z); d[3]=f2tf32(pa[i].w);
        }
#pragma unroll
        for (int i = 0; i < 2; i++) {
            unsigned* d = &Bs[bn[i]*36 + bk[i]];
            d[0]=f2tf32(pb[i].x); d[1]=f2tf32(pb[i].y); d[2]=f2tf32(pb[i].z); d[3]=f2tf32(pb[i].w);
        }
    };

    float acc[2][4][4];
#pragma unroll
    for (int i = 0; i < 2; i++)
#pragma unroll
        for (int j = 0; j < 4; j++)
#pragma unroll
            for (int k = 0; k < 4; k++) acc[i][j][k] = 0.f;

    load_tile(0);
    store_tile();
    __syncthreads();

    for (int it = 0; it < nit; it++) {
        if (it + 1 < nit) load_tile((it + 1) * BKg);
#pragma unroll
        for (int ks = 0; ks < 4; ks++) {
            int kb = ks * 8;
            unsigned af[2][4], bf[4][2];
#pragma unroll
            for (int mi = 0; mi < 2; mi++) {
                int mr = wm*32 + mi*16 + g;
                af[mi][0] = As[ mr      *36 + kb + t];
                af[mi][1] = As[(mr + 8) *36 + kb + t];
                af[mi][2] = As[ mr      *36 + kb + t + 4];
                af[mi][3] = As[(mr + 8) *36 + kb + t + 4];
            }
#pragma unroll
            for (int ni = 0; ni < 4; ni++) {
                int nr = wn*32 + ni*8 + g;
                bf[ni][0] = Bs[nr*36 + kb + t];
                bf[ni][1] = Bs[nr*36 + kb + t + 4];
            }
#pragma unroll
            for (int mi = 0; mi < 2; mi++)
#pragma unroll
                for (int ni = 0; ni < 4; ni++)
                    mma_tf32(acc[mi][ni], af[mi], bf[ni]);
        }
        if (it + 1 < nit) {
            __syncthreads();
            store_tile();
            __syncthreads();
        }
    }

    // ---------------- epilogue ----------------
#pragma unroll
    for (int mi = 0; mi < 2; mi++) {
#pragma unroll
        for (int half = 0; half < 2; half++) {      // c0/c1 then c2/c3
            long m = m0 + wm*32 + mi*16 + g + half*8;
            long orow;
            if (EPI == 1) {
                int p   = (int)(m & 63);
                int win = (int)((m >> 6) & 63);
                int b   = (int)(m >> 12);
                int r = p >> 3, c = p & 7;
                int wi = win >> 3, wj = win & 7;
                int h = (wi*8 + r + 4) & 63;
                int w = (wj*8 + c + 4) & 63;
                orow = (long)((b*64 + h)*64 + w);
            } else {
                orow = m;
            }
#pragma unroll
            for (int ni = 0; ni < 4; ni++) {
                int col = n0 + wn*32 + ni*8 + t*2;
                float v0 = acc[mi][ni][half*2 + 0] + __ldg(bias + col);
                float v1 = acc[mi][ni][half*2 + 1] + __ldg(bias + col + 1);
                if (EPI == 1) {
                    const float2 rv = *(const float2*)(res + orow * (long)N + col);
                    v0 += rv.x; v1 += rv.y;
                } else if (EPI == 2) {
                    v0 = 0.5f * v0 * (1.f + erff(v0 * 0.70710678118654752f));
                    v1 = 0.5f * v1 * (1.f + erff(v1 * 0.70710678118654752f));
                } else if (EPI == 3) {
                    const float2 rv = *(const float2*)(res + m * (long)N + col);
                    v0 += rv.x; v1 += rv.y;
                }
                *(float2*)(out + orow * (long)N + col) = make_float2(v0, v1);
            }
        }
    }
}

// ---------------- windowed attention: one block per (window, head), 64 threads ----------------
__global__ __launch_bounds__(64) void attn_kernel(
        const float* __restrict__ qkv,
        const float* __restrict__ rpp,
        float* __restrict__ ao) {
    int wg   = blockIdx.x;
    int head = blockIdx.y;
    int t    = threadIdx.x;
    int win  = wg & 63;
    int wi = win >> 3, wj = win & 7;

    __shared__ float ks[64][36];
    __shared__ float vs[64][36];
    __shared__ float S[64][65];
    __shared__ float biasS[228];

    long rowbase = (long)(wg*64 + t) * QKVW;
    float q[32];
    {
        const float4* qp = (const float4*)(qkv + rowbase + head*HDIM);
        const float4* kp = (const float4*)(qkv + rowbase + (NHEAD + head)*HDIM);
        const float4* vp = (const float4*)(qkv + rowbase + (2*NHEAD + head)*HDIM);
#pragma unroll
        for (int d4 = 0; d4 < 8; d4++) {
            float4 qv = qp[d4];
            q[4*d4+0] = qv.x; q[4*d4+1] = qv.y; q[4*d4+2] = qv.z; q[4*d4+3] = qv.w;
            ((float4*)&ks[t][0])[d4] = kp[d4];
            ((float4*)&vs[t][0])[d4] = vp[d4];
        }
    }
    for (int i = t; i < 225; i += 64) biasS[i] = rpp[head*225 + i];
    __syncthreads();

    const float scale = 0.17677669529663687f;
    int r1 = t >> 3, c1 = t & 7;
    bool mi = (wi == 7), mj = (wj == 7);
    bool q_r = (r1 < 4), q_c = (c1 < 4);

    float mx = -1e30f;
#pragma unroll 4
    for (int j = 0; j < 64; j++) {
        int r2 = j >> 3, c2 = j & 7;
        const float4* kr = (const float4*)&ks[j][0];
        float s = 0.f;
#pragma unroll
        for (int d4 = 0; d4 < 8; d4++) {
            float4 kv = kr[d4];
            s += q[4*d4+0]*kv.x + q[4*d4+1]*kv.y + q[4*d4+2]*kv.z + q[4*d4+3]*kv.w;
        }
        s = s * scale + biasS[(r1 - r2 + 7)*15 + (c1 - c2 + 7)];
        bool msk = (mi && (q_r != (r2 < 4))) || (mj && (q_c != (c2 < 4)));
        if (msk) s = -1e30f;
        S[t][j] = s;
        mx = fmaxf(mx, s);
    }
    float sum = 0.f;
#pragma unroll 4
    for (int j = 0; j < 64; j++) {
        float p = __expf(S[t][j] - mx);
        S[t][j] = p;
        sum += p;
    }
    float o[32] = {};
#pragma unroll 2
    for (int j = 0; j < 64; j++) {
        float p = S[t][j];
        const float4* vr = (const float4*)&vs[j][0];
#pragma unroll
        for (int d4 = 0; d4 < 8; d4++) {
            float4 vv = vr[d4];
            o[4*d4+0] += p*vv.x; o[4*d4+1] += p*vv.y;
            o[4*d4+2] += p*vv.z; o[4*d4+3] += p*vv.w;
        }
    }
    float inv = 1.f / sum;
    float* orow = ao + (long)(wg*64 + t) * C_ + head*HDIM;
#pragma unroll
    for (int d4 = 0; d4 < 8; d4++) {
        float4 ov = make_float4(o[4*d4]*inv, o[4*d4+1]*inv, o[4*d4+2]*inv, o[4*d4+3]*inv);
        ((float4*)orow)[d4] = ov;
    }
}

// ---------------- launcher ----------------
extern "C" void kernel_launch(void* const* d_in, const int* in_sizes, int n_in,
                              void* d_out, int out_size) {
    const float* x      = (const float*)d_in[0];
    const float* ln1_g  = (const float*)d_in[1];
    const float* ln1_b  = (const float*)d_in[2];
    const float* qkv_w  = (const float*)d_in[3];
    const float* qkv_b  = (const float*)d_in[4];
    const float* rpp    = (const float*)d_in[5];
    const float* lin_w  = (const float*)d_in[6];
    const float* lin_b  = (const float*)d_in[7];
    const float* ln2_g  = (const float*)d_in[8];
    const float* ln2_b  = (const float*)d_in[9];
    const float* mlp_w1 = (const float*)d_in[10];
    const float* mlp_b1 = (const float*)d_in[11];
    const float* mlp_w2 = (const float*)d_in[12];
    const float* mlp_b2 = (const float*)d_in[13];
    float* out = (float*)d_out;

    float *YZ, *QKV, *XMID, *Hm;
    cudaGetSymbolAddress((void**)&YZ,   g_YZ);
    cudaGetSymbolAddress((void**)&QKV,  g_QKV);
    cudaGetSymbolAddress((void**)&XMID, g_XMID);
    cudaGetSymbolAddress((void**)&Hm,   g_H);
    float* AO = Hm;

    const int LN_BLOCKS = NTOK / 8;
    const int MBT = NTOK / 128;     // 1024 row tiles

    // 1) LN1 + shift-roll + window partition
    ln_kernel<true><<<LN_BLOCKS, 256>>>(x, ln1_g, ln1_b, YZ);
    // 2) qkv projection (+bias), tf32 tensor cores
    gemm_tc<0><<<dim3(QKVW/64, MBT), 256>>>(YZ, qkv_w, qkv_b, nullptr, QKV, NTOK, QKVW, C_);
    // 3) windowed attention
    attn_kernel<<<dim3(2048, NHEAD), 64>>>(QKV, rpp, AO);
    // 4) output projection + un-window/un-roll + residual
    gemm_tc<1><<<dim3(C_/64, MBT), 256>>>(AO, lin_w, lin_b, x, XMID, NTOK, C_, C_);
    // 5) LN2
    ln_kernel<false><<<LN_BLOCKS, 256>>>(XMID, ln2_g, ln2_b, YZ);
    // 6) MLP up + exact GELU
    gemm_tc<2><<<dim3(MLPD/64, MBT), 256>>>(YZ, mlp_w1, mlp_b1, nullptr, Hm, NTOK, MLPD, C_);
    // 7) MLP down + residual -> out
    gemm_tc<3><<<dim3(C_/64, MBT), 256>>>(Hm, mlp_w2, mlp_b2, XMID, out, NTOK, C_, MLPD);
}